// round 14
// baseline (speedup 1.0000x reference)
#include <cuda_runtime.h>
#include <cuda_fp16.h>

#define NN 100000
#define EE 1600000
typedef unsigned long long ull;

// ---------------- scratch (static device globals) ----------------------------
__device__ float    g_acc[NN * 64];   // agg0 out -> gat1 agg out (t1)
__device__ float    g_h  [NN * 64];   // relu(GCN out)  (fp32)
__device__ __half   g_xh [NN * 64];   // fp16 copy of x (gather-only)
__device__ __half   g_h1h[NN * 64];   // GAT1 h (fp16)
__device__ __half   g_h2h[NN * 32];   // GAT2 h (fp16)
__device__ float    g_ssrc[NN];
__device__ float    g_sdst[NN];
__device__ unsigned g_cnt[NN];        // in-degree (excl self)
__device__ unsigned g_off[NN];        // CSR offsets (exclusive scan of cnt)
__device__ int      g_cur[NN];        // scatter cursors
__device__ unsigned g_part[512];      // scan partials
__device__ int      g_csr[EE];        // src ids grouped by dst

// ---------------- helpers ----------------------------------------------------
__device__ __forceinline__ float lrelu(float z) { return z > 0.f ? z : 0.2f * z; }

__device__ __forceinline__ ull pack2(float a) {
    ull r; asm("mov.b64 %0, {%1, %1};" : "=l"(r) : "f"(a)); return r;
}
__device__ __forceinline__ void ffma2(ull& d, ull a, ull b) {
    asm("fma.rn.f32x2 %0, %1, %2, %0;" : "+l"(d) : "l"(a), "l"(b));
}
__device__ __forceinline__ float2 upk(ull v) {
    float2 f; asm("mov.b64 {%0, %1}, %2;" : "=f"(f.x), "=f"(f.y) : "l"(v)); return f;
}

// convert uint4 (8 halves) into 8 floats
__device__ __forceinline__ void h8_to_f8(uint4 u, float* f) {
    float2 f0 = __half22float2(*(__half2*)&u.x);
    float2 f1 = __half22float2(*(__half2*)&u.y);
    float2 f2 = __half22float2(*(__half2*)&u.z);
    float2 f3 = __half22float2(*(__half2*)&u.w);
    f[0] = f0.x; f[1] = f0.y; f[2] = f1.x; f[3] = f1.y;
    f[4] = f2.x; f[5] = f2.y; f[6] = f3.x; f[7] = f3.y;
}

// ---------------- x -> fp16 copy ----------------------------------------------
__global__ void k_xtoh(const float4* __restrict__ x4, int n) {
    int idx = blockIdx.x * blockDim.x + threadIdx.x;   // over n*8 uint4 slots
    if (idx >= n * 8) return;
    float4 a = x4[idx * 2];
    float4 b = x4[idx * 2 + 1];
    uint4 u;
    *(__half2*)&u.x = __float22half2_rn(make_float2(a.x, a.y));
    *(__half2*)&u.y = __float22half2_rn(make_float2(a.z, a.w));
    *(__half2*)&u.z = __float22half2_rn(make_float2(b.x, b.y));
    *(__half2*)&u.w = __float22half2_rn(make_float2(b.z, b.w));
    ((uint4*)g_xh)[idx] = u;
}

// ---------------- CSR build ---------------------------------------------------
__global__ void k_zero_cnt(int n) {
    int i = blockIdx.x * blockDim.x + threadIdx.x;
    if (i < n) g_cnt[i] = 0u;
}
__global__ void k_hist(const int* __restrict__ dst, int e) {
    int t = blockIdx.x * blockDim.x + threadIdx.x;
    if (t < e) atomicAdd(&g_cnt[dst[t]], 1u);
}
__global__ void k_scanA(int n) {
    __shared__ unsigned s[256];
    int lt = threadIdx.x, i = blockIdx.x * 256 + lt;
    unsigned v = (i < n) ? g_cnt[i] : 0u;
    s[lt] = v; __syncthreads();
#pragma unroll
    for (int ofs = 1; ofs < 256; ofs <<= 1) {
        unsigned t = (lt >= ofs) ? s[lt - ofs] : 0u;
        __syncthreads();
        s[lt] += t;
        __syncthreads();
    }
    if (i < n) g_off[i] = s[lt] - v;
    if (lt == 255) g_part[blockIdx.x] = s[255];
}
__global__ void k_scanB(int nb) {
    __shared__ unsigned s[512];
    int lt = threadIdx.x;
    unsigned v = (lt < nb) ? g_part[lt] : 0u;
    s[lt] = v; __syncthreads();
#pragma unroll
    for (int ofs = 1; ofs < 512; ofs <<= 1) {
        unsigned t = (lt >= ofs) ? s[lt - ofs] : 0u;
        __syncthreads();
        s[lt] += t;
        __syncthreads();
    }
    if (lt < nb) g_part[lt] = s[lt] - v;
}
__global__ void k_scanC(int n) {
    int i = blockIdx.x * 256 + threadIdx.x;
    if (i < n) {
        unsigned o = g_off[i] + g_part[blockIdx.x];
        g_off[i] = o;
        g_cur[i] = (int)o;
    }
}
__global__ void k_scatter(const int* __restrict__ src, const int* __restrict__ dst, int e) {
    int t = blockIdx.x * blockDim.x + threadIdx.x;
    if (t >= e) return;
    int d = dst[t];
    int pos = atomicAdd(&g_cur[d], 1);
    g_csr[pos] = src[t];
}

// ---------------- GCN neighbor sum (fp16 gather, 8 lanes/node, unroll 2) ------
__global__ void k_agg0(int n) {
    int t = blockIdx.x * blockDim.x + threadIdx.x;
    int g = t >> 3, q = t & 7;
    if (g >= n) return;
    const uint4* xh = (const uint4*)g_xh;
    unsigned o = g_off[g], c = g_cnt[g];
    float a[8] = {0.f, 0.f, 0.f, 0.f, 0.f, 0.f, 0.f, 0.f};
    float b[8] = {0.f, 0.f, 0.f, 0.f, 0.f, 0.f, 0.f, 0.f};
    unsigned j = 0;
    for (; j + 2 <= c; j += 2) {
        int s0 = __ldg(&g_csr[o + j]);
        int s1 = __ldg(&g_csr[o + j + 1]);
        uint4 u0 = xh[(size_t)s0 * 8 + q];
        uint4 u1 = xh[(size_t)s1 * 8 + q];
        float v0[8], v1[8];
        h8_to_f8(u0, v0);
        h8_to_f8(u1, v1);
#pragma unroll
        for (int i = 0; i < 8; i++) { a[i] += v0[i]; b[i] += v1[i]; }
    }
    if (j < c) {
        int s0 = __ldg(&g_csr[o + j]);
        float v0[8];
        h8_to_f8(xh[(size_t)s0 * 8 + q], v0);
#pragma unroll
        for (int i = 0; i < 8; i++) a[i] += v0[i];
    }
#pragma unroll
    for (int i = 0; i < 8; i++) a[i] += b[i];
    float4* op = (float4*)(g_acc + (size_t)g * 64 + q * 8);
    op[0] = make_float4(a[0], a[1], a[2], a[3]);
    op[1] = make_float4(a[4], a[5], a[6], a[7]);
}

// ---------------- tiled GEMM core (packed f32x2 FFMA) -------------------------
template<int NC2>
__device__ __forceinline__ void gemm_core2(const float* __restrict__ sA,
                                           const float* __restrict__ sW,
                                           ull* acc, int ri, int ci) {
    const float* a0 = sA + ri * 8 * 68;
#pragma unroll 2
    for (int k = 0; k < 64; k++) {
        ull w = ((const ull*)sW)[k * NC2 + ci];
#pragma unroll
        for (int j = 0; j < 8; j++) {
            ull av = pack2(a0[j * 68 + k]);
            ffma2(acc[j], av, w);
        }
    }
}

// GCN: h = relu(((acc+x)*dinv)@Wout + x@Wroot + bout). 512 thr, 128-row tile.
__global__ __launch_bounds__(512) void k_gemm0(
        const float4* __restrict__ x4, const float* __restrict__ Wout,
        const float* __restrict__ bout, const float* __restrict__ Wroot, int n) {
    extern __shared__ float smem[];
    float* sA = smem;                 // 128*68
    float* sW = smem + 128 * 68;      // 2*4096
    int tid = threadIdx.x;
    for (int i = tid; i < 4096; i += 512) { sW[i] = Wout[i]; sW[4096 + i] = Wroot[i]; }
    int rbase = blockIdx.x * 128;
#pragma unroll
    for (int it = 0; it < 4; it++) {
        int idx = it * 512 + tid, row = idx >> 4, k4 = idx & 15;
        int gr = rbase + row;
        float4 v = make_float4(0.f, 0.f, 0.f, 0.f);
        if (gr < n) {
            float4 a = ((const float4*)g_acc)[(size_t)gr * 16 + k4];
            float4 xv = x4[(size_t)gr * 16 + k4];
            float di = 1.f / ((float)g_cnt[gr] + 1.f);
            v = make_float4((a.x + xv.x) * di, (a.y + xv.y) * di,
                            (a.z + xv.z) * di, (a.w + xv.w) * di);
        }
        *(float4*)&sA[row * 68 + k4 * 4] = v;
    }
    __syncthreads();
    int ci = tid & 31, ri = tid >> 5;
    ull acc[8];
#pragma unroll
    for (int i = 0; i < 8; i++) acc[i] = 0ull;
    gemm_core2<32>(sA, sW, acc, ri, ci);
    __syncthreads();
#pragma unroll
    for (int it = 0; it < 4; it++) {
        int idx = it * 512 + tid, row = idx >> 4, k4 = idx & 15;
        int gr = rbase + row;
        float4 v = make_float4(0.f, 0.f, 0.f, 0.f);
        if (gr < n) v = x4[(size_t)gr * 16 + k4];
        *(float4*)&sA[row * 68 + k4 * 4] = v;
    }
    __syncthreads();
    gemm_core2<32>(sA, sW + 4096, acc, ri, ci);
    float2 bv = __ldg((const float2*)bout + ci);
#pragma unroll
    for (int j = 0; j < 8; j++) {
        int gr = rbase + ri * 8 + j;
        if (gr < n) {
            float2 p = upk(acc[j]);
            float2 o = make_float2(fmaxf(p.x + bv.x, 0.f), fmaxf(p.y + bv.y, 0.f));
            ((float2*)g_h)[(size_t)gr * 32 + ci] = o;
        }
    }
}

// GAT1: h1 = g_h @ W1 (stored fp16); fused dots (warp-reduce). 512 thr.
__global__ __launch_bounds__(512) void k_gemm1(
        const float* __restrict__ W1, const float* __restrict__ as1,
        const float* __restrict__ ad1, int n) {
    extern __shared__ float smem[];
    float* sA = smem;
    float* sW = smem + 128 * 68;
    int tid = threadIdx.x;
    for (int i = tid; i < 4096; i += 512) sW[i] = W1[i];
    int rbase = blockIdx.x * 128;
#pragma unroll
    for (int it = 0; it < 4; it++) {
        int idx = it * 512 + tid, row = idx >> 4, k4 = idx & 15;
        int gr = rbase + row;
        float4 v = make_float4(0.f, 0.f, 0.f, 0.f);
        if (gr < n) v = ((const float4*)g_h)[(size_t)gr * 16 + k4];
        *(float4*)&sA[row * 68 + k4 * 4] = v;
    }
    __syncthreads();
    int ci = tid & 31, ri = tid >> 5;
    ull acc[8];
#pragma unroll
    for (int i = 0; i < 8; i++) acc[i] = 0ull;
    gemm_core2<32>(sA, sW, acc, ri, ci);
    float2 asv = __ldg((const float2*)as1 + ci);
    float2 adv = __ldg((const float2*)ad1 + ci);
#pragma unroll
    for (int j = 0; j < 8; j++) {
        int gr = rbase + ri * 8 + j;
        float2 p = upk(acc[j]);
        if (gr < n)
            ((__half2*)g_h1h)[(size_t)gr * 32 + ci] = __float22half2_rn(p);
        float ps = p.x * asv.x + p.y * asv.y;
        float pd = p.x * adv.x + p.y * adv.y;
#pragma unroll
        for (int o = 16; o; o >>= 1) {
            ps += __shfl_xor_sync(0xFFFFFFFFu, ps, o);
            pd += __shfl_xor_sync(0xFFFFFFFFu, pd, o);
        }
        if (ci == 0 && gr < n) { g_ssrc[gr] = ps; g_sdst[gr] = pd; }
    }
}

// GAT2: h2 = relu(t1 + b1) @ W2 (stored fp16); fused dots. 256 thr.
__global__ __launch_bounds__(256) void k_gemm2(
        const float* __restrict__ W2, const float* __restrict__ b1,
        const float* __restrict__ as2, const float* __restrict__ ad2, int n) {
    extern __shared__ float smem[];
    float* sA = smem;
    float* sW = smem + 128 * 68;      // 2048
    int tid = threadIdx.x;
    for (int i = tid; i < 2048; i += 256) sW[i] = W2[i];
    int rbase = blockIdx.x * 128;
#pragma unroll
    for (int it = 0; it < 8; it++) {
        int idx = it * 256 + tid, row = idx >> 4, k4 = idx & 15;
        int gr = rbase + row;
        float4 v = make_float4(0.f, 0.f, 0.f, 0.f);
        if (gr < n) {
            float4 a = ((const float4*)g_acc)[(size_t)gr * 16 + k4];
            float4 b = __ldg((const float4*)b1 + k4);
            v = make_float4(fmaxf(a.x + b.x, 0.f), fmaxf(a.y + b.y, 0.f),
                            fmaxf(a.z + b.z, 0.f), fmaxf(a.w + b.w, 0.f));
        }
        *(float4*)&sA[row * 68 + k4 * 4] = v;
    }
    __syncthreads();
    int ci = tid & 15, ri = tid >> 4;
    ull acc[8];
#pragma unroll
    for (int i = 0; i < 8; i++) acc[i] = 0ull;
    gemm_core2<16>(sA, sW, acc, ri, ci);
    float2 asv = __ldg((const float2*)as2 + ci);
    float2 adv = __ldg((const float2*)ad2 + ci);
#pragma unroll
    for (int j = 0; j < 8; j++) {
        int gr = rbase + ri * 8 + j;
        float2 p = upk(acc[j]);
        if (gr < n)
            ((__half2*)g_h2h)[(size_t)gr * 16 + ci] = __float22half2_rn(p);
        float ps = p.x * asv.x + p.y * asv.y;
        float pd = p.x * adv.x + p.y * adv.y;
#pragma unroll
        for (int o = 8; o; o >>= 1) {
            ps += __shfl_xor_sync(0xFFFFFFFFu, ps, o);
            pd += __shfl_xor_sync(0xFFFFFFFFu, pd, o);
        }
        if (ci == 0 && gr < n) { g_ssrc[gr] = ps; g_sdst[gr] = pd; }
    }
}

// ---------------- GAT aggregation: split-state online softmax, fp16 gathers ---
// C = feature count. L = C/8 lanes per node; each lane owns 8 halves (16B).
template<int C, bool FINAL>
__global__ void k_gat_agg(float* __restrict__ out_arg,
                          const float* __restrict__ bias, int n) {
    constexpr int L = C / 8;
    const uint4* h4 = (C == 64) ? (const uint4*)g_h1h : (const uint4*)g_h2h;
    float* outp = FINAL ? out_arg : g_acc;
    int t = blockIdx.x * blockDim.x + threadIdx.x;
    int g = t / L, q = t % L;
    if (g >= n) return;
    unsigned o = g_off[g], c = g_cnt[g];
    float sdp = g_sdst[g];
    float m0 = lrelu(g_ssrc[g] + sdp);
    float a0[8];
    h8_to_f8(h4[(size_t)g * L + q], a0);
    float d0 = 1.f;
    float m1 = -3.0e38f;
    float a1[8] = {0.f, 0.f, 0.f, 0.f, 0.f, 0.f, 0.f, 0.f};
    float d1 = 0.f;
    unsigned j = 0;
    for (; j + 2 <= c; j += 2) {
        int s0 = __ldg(&g_csr[o + j]);
        int s1 = __ldg(&g_csr[o + j + 1]);
        float ss0 = g_ssrc[s0];
        float ss1 = g_ssrc[s1];
        uint4 u0 = h4[(size_t)s0 * L + q];
        uint4 u1 = h4[(size_t)s1 * L + q];
        float v0[8], v1[8];
        h8_to_f8(u0, v0);
        h8_to_f8(u1, v1);
        float l0 = lrelu(ss0 + sdp);
        float l1 = lrelu(ss1 + sdp);
        float w0;
        if (l0 > m0) {
            float r = __expf(m0 - l0);
#pragma unroll
            for (int i = 0; i < 8; i++) a0[i] *= r;
            d0 *= r; m0 = l0; w0 = 1.f;
        } else w0 = __expf(l0 - m0);
#pragma unroll
        for (int i = 0; i < 8; i++) a0[i] = fmaf(w0, v0[i], a0[i]);
        d0 += w0;
        float w1;
        if (l1 > m1) {
            float r = __expf(m1 - l1);
#pragma unroll
            for (int i = 0; i < 8; i++) a1[i] *= r;
            d1 *= r; m1 = l1; w1 = 1.f;
        } else w1 = __expf(l1 - m1);
#pragma unroll
        for (int i = 0; i < 8; i++) a1[i] = fmaf(w1, v1[i], a1[i]);
        d1 += w1;
    }
    if (j < c) {
        int s0 = __ldg(&g_csr[o + j]);
        float ss0 = g_ssrc[s0];
        float v0[8];
        h8_to_f8(h4[(size_t)s0 * L + q], v0);
        float l0 = lrelu(ss0 + sdp);
        float w0;
        if (l0 > m0) {
            float r = __expf(m0 - l0);
#pragma unroll
            for (int i = 0; i < 8; i++) a0[i] *= r;
            d0 *= r; m0 = l0; w0 = 1.f;
        } else w0 = __expf(l0 - m0);
#pragma unroll
        for (int i = 0; i < 8; i++) a0[i] = fmaf(w0, v0[i], a0[i]);
        d0 += w0;
    }
    float den;
    if (m0 >= m1) {
        float r = __expf(m1 - m0);
#pragma unroll
        for (int i = 0; i < 8; i++) a0[i] = fmaf(r, a1[i], a0[i]);
        den = fmaf(r, d1, d0);
    } else {
        float r = __expf(m0 - m1);
#pragma unroll
        for (int i = 0; i < 8; i++) a0[i] = fmaf(r, a0[i], a1[i]);
        den = fmaf(r, d0, d1);
    }
    float rd = 1.f / den;
    float4 r0 = make_float4(a0[0] * rd, a0[1] * rd, a0[2] * rd, a0[3] * rd);
    float4 r1 = make_float4(a0[4] * rd, a0[5] * rd, a0[6] * rd, a0[7] * rd);
    if (FINAL) {
        float4 b0 = __ldg((const float4*)bias + q * 2);
        float4 b1v = __ldg((const float4*)bias + q * 2 + 1);
        r0.x += b0.x; r0.y += b0.y; r0.z += b0.z; r0.w += b0.w;
        r1.x += b1v.x; r1.y += b1v.y; r1.z += b1v.z; r1.w += b1v.w;
    }
    float4* op = (float4*)(outp + (size_t)g * C + q * 8);
    op[0] = r0;
    op[1] = r1;
}

// ---------------- launch ------------------------------------------------------
extern "C" void kernel_launch(void* const* d_in, const int* in_sizes, int n_in,
                              void* d_out, int out_size) {
    const float* x    = (const float*)d_in[0];
    const int*   ei   = (const int*)  d_in[1];
    const float* Wout = (const float*)d_in[2];
    const float* bout = (const float*)d_in[3];
    const float* Wroot= (const float*)d_in[4];
    const float* W1   = (const float*)d_in[5];
    const float* as1  = (const float*)d_in[6];
    const float* ad1  = (const float*)d_in[7];
    const float* b1   = (const float*)d_in[8];
    const float* W2   = (const float*)d_in[9];
    const float* as2  = (const float*)d_in[10];
    const float* ad2  = (const float*)d_in[11];
    const float* b2   = (const float*)d_in[12];

    int n = in_sizes[0] / 64;
    int e = in_sizes[1] / 2;
    const int* src = ei;
    const int* dst = ei + e;

    cudaFuncSetAttribute(k_gemm0, cudaFuncAttributeMaxDynamicSharedMemorySize, 128*68*4 + 32768);
    cudaFuncSetAttribute(k_gemm1, cudaFuncAttributeMaxDynamicSharedMemorySize, 128*68*4 + 16384);

    const int TB = 256;
    int nbs   = (n + 255) / 256;
    int nb_e  = (e + TB - 1) / TB;
    int nb_g  = (n + 127) / 128;
    int nb_8  = (n * 8 + TB - 1) / TB;   // agg0 + gat_agg<64>: L=8
    int nb_4  = (n * 4 + TB - 1) / TB;   // gat_agg<32>: L=4

    // CSR build + fp16 x copy (independent; overlap on stream)
    k_zero_cnt<<<nbs, TB>>>(n);
    k_xtoh    <<<nb_8, TB>>>((const float4*)x, n);
    k_hist    <<<nb_e, TB>>>(dst, e);
    k_scanA   <<<nbs, 256>>>(n);
    k_scanB   <<<1, 512>>>(nbs);
    k_scanC   <<<nbs, 256>>>(n);
    k_scatter <<<nb_e, TB>>>(src, dst, e);

    // Layer 0: ClusterGCN
    k_agg0 <<<nb_8, TB>>>(n);
    k_gemm0<<<nb_g, 512, 128*68*4 + 32768>>>((const float4*)x, Wout, bout, Wroot, n);

    // Layer 1: GAT(64->64)
    k_gemm1<<<nb_g, 512, 128*68*4 + 16384>>>(W1, as1, ad1, n);
    k_gat_agg<64, false><<<nb_8, TB>>>(nullptr, nullptr, n);

    // Layer 2: GAT(64->32)
    k_gemm2<<<nb_g, 256, 128*68*4 + 8192>>>(W2, b1, as2, ad2, n);
    k_gat_agg<32, true><<<nb_4, TB>>>((float*)d_out, b2, n);
}

// round 15
// speedup vs baseline: 1.0289x; 1.0289x over previous
#include <cuda_runtime.h>
#include <cuda_fp16.h>

#define NN 100000
#define EE 1600000
typedef unsigned long long ull;

// ---------------- scratch (static device globals) ----------------------------
__device__ float    g_acc[NN * 64];   // agg0 out -> gat1 agg out (t1)
__device__ float    g_h  [NN * 64];   // relu(GCN out)  (fp32)
__device__ __half   g_h1h[NN * 64];   // GAT1 h (fp16)
__device__ __half   g_h2h[NN * 32];   // GAT2 h (fp16)
__device__ float    g_ssrc[NN];
__device__ float    g_sdst[NN];
__device__ unsigned g_cnt[NN];        // in-degree (excl self)
__device__ unsigned g_off[NN];        // CSR offsets
__device__ int      g_cur[NN];        // scatter cursors
__device__ unsigned g_total;          // offset allocator
__device__ int      g_csr[EE];        // src ids grouped by dst

// ---------------- helpers ----------------------------------------------------
__device__ __forceinline__ float lrelu(float z) { return z > 0.f ? z : 0.2f * z; }

__device__ __forceinline__ ull pack2(float a) {
    ull r; asm("mov.b64 %0, {%1, %1};" : "=l"(r) : "f"(a)); return r;
}
__device__ __forceinline__ void ffma2(ull& d, ull a, ull b) {
    asm("fma.rn.f32x2 %0, %1, %2, %0;" : "+l"(d) : "l"(a), "l"(b));
}
__device__ __forceinline__ float2 upk(ull v) {
    float2 f; asm("mov.b64 {%0, %1}, %2;" : "=f"(f.x), "=f"(f.y) : "l"(v)); return f;
}

// convert uint4 (8 halves) into 8 floats
__device__ __forceinline__ void h8_to_f8(uint4 u, float* f) {
    float2 f0 = __half22float2(*(__half2*)&u.x);
    float2 f1 = __half22float2(*(__half2*)&u.y);
    float2 f2 = __half22float2(*(__half2*)&u.z);
    float2 f3 = __half22float2(*(__half2*)&u.w);
    f[0] = f0.x; f[1] = f0.y; f[2] = f1.x; f[3] = f1.y;
    f[4] = f2.x; f[5] = f2.y; f[6] = f3.x; f[7] = f3.y;
}

// ---------------- CSR build ---------------------------------------------------
__global__ void k_zero_cnt(int n) {
    int i = blockIdx.x * blockDim.x + threadIdx.x;
    if (i < n) g_cnt[i] = 0u;
    if (i == 0) g_total = 0u;
}
__global__ void k_hist(const int* __restrict__ dst, int e) {
    int t = blockIdx.x * blockDim.x + threadIdx.x;
    if (t < e) atomicAdd(&g_cnt[dst[t]], 1u);
}
// single-kernel offsets: block-local inclusive scan + atomic block base.
// Offsets are run-order dependent (disjoint ranges), which only permutes CSR
// segment placement — per-node neighbor sets are unchanged.
__global__ void k_offsets(int n) {
    __shared__ unsigned s[256];
    __shared__ unsigned sbase;
    int lt = threadIdx.x, i = blockIdx.x * 256 + lt;
    unsigned v = (i < n) ? g_cnt[i] : 0u;
    s[lt] = v; __syncthreads();
#pragma unroll
    for (int ofs = 1; ofs < 256; ofs <<= 1) {
        unsigned t = (lt >= ofs) ? s[lt - ofs] : 0u;
        __syncthreads();
        s[lt] += t;
        __syncthreads();
    }
    if (lt == 255) sbase = atomicAdd(&g_total, s[255]);
    __syncthreads();
    if (i < n) {
        unsigned o = sbase + s[lt] - v;
        g_off[i] = o;
        g_cur[i] = (int)o;
    }
}
__global__ void k_scatter(const int* __restrict__ src, const int* __restrict__ dst, int e) {
    int t = blockIdx.x * blockDim.x + threadIdx.x;
    if (t >= e) return;
    int d = dst[t];
    int pos = atomicAdd(&g_cur[d], 1);
    g_csr[pos] = src[t];
}

// ---------------- GCN neighbor sum (CSR gather, 16 lanes/node, unroll 2) ------
__global__ void k_agg0(const float4* __restrict__ x4, int n) {
    int t = blockIdx.x * blockDim.x + threadIdx.x;
    int g = t >> 4, q = t & 15;
    if (g >= n) return;
    unsigned o = g_off[g], c = g_cnt[g];
    float4 a = make_float4(0.f, 0.f, 0.f, 0.f);
    float4 b = make_float4(0.f, 0.f, 0.f, 0.f);
    unsigned j = 0;
    for (; j + 2 <= c; j += 2) {
        int s0 = __ldg(&g_csr[o + j]);
        int s1 = __ldg(&g_csr[o + j + 1]);
        float4 v0 = x4[(size_t)s0 * 16 + q];
        float4 v1 = x4[(size_t)s1 * 16 + q];
        a.x += v0.x; a.y += v0.y; a.z += v0.z; a.w += v0.w;
        b.x += v1.x; b.y += v1.y; b.z += v1.z; b.w += v1.w;
    }
    if (j < c) {
        int s0 = __ldg(&g_csr[o + j]);
        float4 v0 = x4[(size_t)s0 * 16 + q];
        a.x += v0.x; a.y += v0.y; a.z += v0.z; a.w += v0.w;
    }
    a.x += b.x; a.y += b.y; a.z += b.z; a.w += b.w;
    ((float4*)g_acc)[(size_t)g * 16 + q] = a;
}

// ---------------- tiled GEMM core (packed f32x2 FFMA) -------------------------
template<int NC2>
__device__ __forceinline__ void gemm_core2(const float* __restrict__ sA,
                                           const float* __restrict__ sW,
                                           ull* acc, int ri, int ci) {
    const float* a0 = sA + ri * 8 * 68;
#pragma unroll 2
    for (int k = 0; k < 64; k++) {
        ull w = ((const ull*)sW)[k * NC2 + ci];
#pragma unroll
        for (int j = 0; j < 8; j++) {
            ull av = pack2(a0[j * 68 + k]);
            ffma2(acc[j], av, w);
        }
    }
}

// GCN: h = relu(((acc+x)*dinv)@Wout + x@Wroot + bout). 512 thr, 128-row tile.
__global__ __launch_bounds__(512) void k_gemm0(
        const float4* __restrict__ x4, const float* __restrict__ Wout,
        const float* __restrict__ bout, const float* __restrict__ Wroot, int n) {
    extern __shared__ float smem[];
    float* sA = smem;                 // 128*68
    float* sW = smem + 128 * 68;      // 2*4096
    int tid = threadIdx.x;
    for (int i = tid; i < 4096; i += 512) { sW[i] = Wout[i]; sW[4096 + i] = Wroot[i]; }
    int rbase = blockIdx.x * 128;
#pragma unroll
    for (int it = 0; it < 4; it++) {
        int idx = it * 512 + tid, row = idx >> 4, k4 = idx & 15;
        int gr = rbase + row;
        float4 v = make_float4(0.f, 0.f, 0.f, 0.f);
        if (gr < n) {
            float4 a = ((const float4*)g_acc)[(size_t)gr * 16 + k4];
            float4 xv = x4[(size_t)gr * 16 + k4];
            float di = 1.f / ((float)g_cnt[gr] + 1.f);
            v = make_float4((a.x + xv.x) * di, (a.y + xv.y) * di,
                            (a.z + xv.z) * di, (a.w + xv.w) * di);
        }
        *(float4*)&sA[row * 68 + k4 * 4] = v;
    }
    __syncthreads();
    int ci = tid & 31, ri = tid >> 5;
    ull acc[8];
#pragma unroll
    for (int i = 0; i < 8; i++) acc[i] = 0ull;
    gemm_core2<32>(sA, sW, acc, ri, ci);
    __syncthreads();
#pragma unroll
    for (int it = 0; it < 4; it++) {
        int idx = it * 512 + tid, row = idx >> 4, k4 = idx & 15;
        int gr = rbase + row;
        float4 v = make_float4(0.f, 0.f, 0.f, 0.f);
        if (gr < n) v = x4[(size_t)gr * 16 + k4];
        *(float4*)&sA[row * 68 + k4 * 4] = v;
    }
    __syncthreads();
    gemm_core2<32>(sA, sW + 4096, acc, ri, ci);
    float2 bv = __ldg((const float2*)bout + ci);
#pragma unroll
    for (int j = 0; j < 8; j++) {
        int gr = rbase + ri * 8 + j;
        if (gr < n) {
            float2 p = upk(acc[j]);
            float2 o = make_float2(fmaxf(p.x + bv.x, 0.f), fmaxf(p.y + bv.y, 0.f));
            ((float2*)g_h)[(size_t)gr * 32 + ci] = o;
        }
    }
}

// GAT1: h1 = g_h @ W1 (stored fp16); fused dots (warp-reduce). 512 thr.
__global__ __launch_bounds__(512) void k_gemm1(
        const float* __restrict__ W1, const float* __restrict__ as1,
        const float* __restrict__ ad1, int n) {
    extern __shared__ float smem[];
    float* sA = smem;
    float* sW = smem + 128 * 68;
    int tid = threadIdx.x;
    for (int i = tid; i < 4096; i += 512) sW[i] = W1[i];
    int rbase = blockIdx.x * 128;
#pragma unroll
    for (int it = 0; it < 4; it++) {
        int idx = it * 512 + tid, row = idx >> 4, k4 = idx & 15;
        int gr = rbase + row;
        float4 v = make_float4(0.f, 0.f, 0.f, 0.f);
        if (gr < n) v = ((const float4*)g_h)[(size_t)gr * 16 + k4];
        *(float4*)&sA[row * 68 + k4 * 4] = v;
    }
    __syncthreads();
    int ci = tid & 31, ri = tid >> 5;
    ull acc[8];
#pragma unroll
    for (int i = 0; i < 8; i++) acc[i] = 0ull;
    gemm_core2<32>(sA, sW, acc, ri, ci);
    float2 asv = __ldg((const float2*)as1 + ci);
    float2 adv = __ldg((const float2*)ad1 + ci);
#pragma unroll
    for (int j = 0; j < 8; j++) {
        int gr = rbase + ri * 8 + j;
        float2 p = upk(acc[j]);
        if (gr < n)
            ((__half2*)g_h1h)[(size_t)gr * 32 + ci] = __float22half2_rn(p);
        float ps = p.x * asv.x + p.y * asv.y;
        float pd = p.x * adv.x + p.y * adv.y;
#pragma unroll
        for (int o = 16; o; o >>= 1) {
            ps += __shfl_xor_sync(0xFFFFFFFFu, ps, o);
            pd += __shfl_xor_sync(0xFFFFFFFFu, pd, o);
        }
        if (ci == 0 && gr < n) { g_ssrc[gr] = ps; g_sdst[gr] = pd; }
    }
}

// GAT2: h2 = relu(t1 + b1) @ W2 (stored fp16); fused dots. 256 thr.
__global__ __launch_bounds__(256) void k_gemm2(
        const float* __restrict__ W2, const float* __restrict__ b1,
        const float* __restrict__ as2, const float* __restrict__ ad2, int n) {
    extern __shared__ float smem[];
    float* sA = smem;
    float* sW = smem + 128 * 68;      // 2048
    int tid = threadIdx.x;
    for (int i = tid; i < 2048; i += 256) sW[i] = W2[i];
    int rbase = blockIdx.x * 128;
#pragma unroll
    for (int it = 0; it < 8; it++) {
        int idx = it * 256 + tid, row = idx >> 4, k4 = idx & 15;
        int gr = rbase + row;
        float4 v = make_float4(0.f, 0.f, 0.f, 0.f);
        if (gr < n) {
            float4 a = ((const float4*)g_acc)[(size_t)gr * 16 + k4];
            float4 b = __ldg((const float4*)b1 + k4);
            v = make_float4(fmaxf(a.x + b.x, 0.f), fmaxf(a.y + b.y, 0.f),
                            fmaxf(a.z + b.z, 0.f), fmaxf(a.w + b.w, 0.f));
        }
        *(float4*)&sA[row * 68 + k4 * 4] = v;
    }
    __syncthreads();
    int ci = tid & 15, ri = tid >> 4;
    ull acc[8];
#pragma unroll
    for (int i = 0; i < 8; i++) acc[i] = 0ull;
    gemm_core2<16>(sA, sW, acc, ri, ci);
    float2 asv = __ldg((const float2*)as2 + ci);
    float2 adv = __ldg((const float2*)ad2 + ci);
#pragma unroll
    for (int j = 0; j < 8; j++) {
        int gr = rbase + ri * 8 + j;
        float2 p = upk(acc[j]);
        if (gr < n)
            ((__half2*)g_h2h)[(size_t)gr * 16 + ci] = __float22half2_rn(p);
        float ps = p.x * asv.x + p.y * asv.y;
        float pd = p.x * adv.x + p.y * adv.y;
#pragma unroll
        for (int o = 8; o; o >>= 1) {
            ps += __shfl_xor_sync(0xFFFFFFFFu, ps, o);
            pd += __shfl_xor_sync(0xFFFFFFFFu, pd, o);
        }
        if (ci == 0 && gr < n) { g_ssrc[gr] = ps; g_sdst[gr] = pd; }
    }
}

// ---------------- GAT aggregation: split-state online softmax, fp16 gathers ---
// C = feature count. L = C/8 lanes per node; each lane owns 8 halves (16B).
template<int C, bool FINAL>
__global__ void k_gat_agg(float* __restrict__ out_arg,
                          const float* __restrict__ bias, int n) {
    constexpr int L = C / 8;
    const uint4* h4 = (C == 64) ? (const uint4*)g_h1h : (const uint4*)g_h2h;
    float* outp = FINAL ? out_arg : g_acc;
    int t = blockIdx.x * blockDim.x + threadIdx.x;
    int g = t / L, q = t % L;
    if (g >= n) return;
    unsigned o = g_off[g], c = g_cnt[g];
    float sdp = g_sdst[g];
    float m0 = lrelu(g_ssrc[g] + sdp);
    float a0[8];
    h8_to_f8(h4[(size_t)g * L + q], a0);
    float d0 = 1.f;
    float m1 = -3.0e38f;
    float a1[8] = {0.f, 0.f, 0.f, 0.f, 0.f, 0.f, 0.f, 0.f};
    float d1 = 0.f;
    unsigned j = 0;
    for (; j + 2 <= c; j += 2) {
        int s0 = __ldg(&g_csr[o + j]);
        int s1 = __ldg(&g_csr[o + j + 1]);
        float ss0 = g_ssrc[s0];
        float ss1 = g_ssrc[s1];
        uint4 u0 = h4[(size_t)s0 * L + q];
        uint4 u1 = h4[(size_t)s1 * L + q];
        float v0[8], v1[8];
        h8_to_f8(u0, v0);
        h8_to_f8(u1, v1);
        float l0 = lrelu(ss0 + sdp);
        float l1 = lrelu(ss1 + sdp);
        float w0;
        if (l0 > m0) {
            float r = __expf(m0 - l0);
#pragma unroll
            for (int i = 0; i < 8; i++) a0[i] *= r;
            d0 *= r; m0 = l0; w0 = 1.f;
        } else w0 = __expf(l0 - m0);
#pragma unroll
        for (int i = 0; i < 8; i++) a0[i] = fmaf(w0, v0[i], a0[i]);
        d0 += w0;
        float w1;
        if (l1 > m1) {
            float r = __expf(m1 - l1);
#pragma unroll
            for (int i = 0; i < 8; i++) a1[i] *= r;
            d1 *= r; m1 = l1; w1 = 1.f;
        } else w1 = __expf(l1 - m1);
#pragma unroll
        for (int i = 0; i < 8; i++) a1[i] = fmaf(w1, v1[i], a1[i]);
        d1 += w1;
    }
    if (j < c) {
        int s0 = __ldg(&g_csr[o + j]);
        float ss0 = g_ssrc[s0];
        float v0[8];
        h8_to_f8(h4[(size_t)s0 * L + q], v0);
        float l0 = lrelu(ss0 + sdp);
        float w0;
        if (l0 > m0) {
            float r = __expf(m0 - l0);
#pragma unroll
            for (int i = 0; i < 8; i++) a0[i] *= r;
            d0 *= r; m0 = l0; w0 = 1.f;
        } else w0 = __expf(l0 - m0);
#pragma unroll
        for (int i = 0; i < 8; i++) a0[i] = fmaf(w0, v0[i], a0[i]);
        d0 += w0;
    }
    float den;
    if (m0 >= m1) {
        float r = __expf(m1 - m0);
#pragma unroll
        for (int i = 0; i < 8; i++) a0[i] = fmaf(r, a1[i], a0[i]);
        den = fmaf(r, d1, d0);
    } else {
        float r = __expf(m0 - m1);
#pragma unroll
        for (int i = 0; i < 8; i++) a0[i] = fmaf(r, a0[i], a1[i]);
        den = fmaf(r, d0, d1);
    }
    float rd = 1.f / den;
    float4 r0 = make_float4(a0[0] * rd, a0[1] * rd, a0[2] * rd, a0[3] * rd);
    float4 r1 = make_float4(a0[4] * rd, a0[5] * rd, a0[6] * rd, a0[7] * rd);
    if (FINAL) {
        float4 b0 = __ldg((const float4*)bias + q * 2);
        float4 b1v = __ldg((const float4*)bias + q * 2 + 1);
        r0.x += b0.x; r0.y += b0.y; r0.z += b0.z; r0.w += b0.w;
        r1.x += b1v.x; r1.y += b1v.y; r1.z += b1v.z; r1.w += b1v.w;
    }
    float4* op = (float4*)(outp + (size_t)g * C + q * 8);
    op[0] = r0;
    op[1] = r1;
}

// ---------------- launch ------------------------------------------------------
extern "C" void kernel_launch(void* const* d_in, const int* in_sizes, int n_in,
                              void* d_out, int out_size) {
    const float* x    = (const float*)d_in[0];
    const int*   ei   = (const int*)  d_in[1];
    const float* Wout = (const float*)d_in[2];
    const float* bout = (const float*)d_in[3];
    const float* Wroot= (const float*)d_in[4];
    const float* W1   = (const float*)d_in[5];
    const float* as1  = (const float*)d_in[6];
    const float* ad1  = (const float*)d_in[7];
    const float* b1   = (const float*)d_in[8];
    const float* W2   = (const float*)d_in[9];
    const float* as2  = (const float*)d_in[10];
    const float* ad2  = (const float*)d_in[11];
    const float* b2   = (const float*)d_in[12];

    int n = in_sizes[0] / 64;
    int e = in_sizes[1] / 2;
    const int* src = ei;
    const int* dst = ei + e;

    cudaFuncSetAttribute(k_gemm0, cudaFuncAttributeMaxDynamicSharedMemorySize, 128*68*4 + 32768);
    cudaFuncSetAttribute(k_gemm1, cudaFuncAttributeMaxDynamicSharedMemorySize, 128*68*4 + 16384);

    const int TB = 256;
    int nbs   = (n + 255) / 256;
    int nb_e  = (e + TB - 1) / TB;
    int nb_g  = (n + 127) / 128;
    int nb_16 = (n * 16 + TB - 1) / TB;
    int nb_8  = (n * 8 + TB - 1) / TB;   // gat_agg<64>: L=8
    int nb_4  = (n * 4 + TB - 1) / TB;   // gat_agg<32>: L=4

    // CSR build (single-kernel offsets)
    k_zero_cnt<<<nbs, TB>>>(n);
    k_hist    <<<nb_e, TB>>>(dst, e);
    k_offsets <<<nbs, 256>>>(n);
    k_scatter <<<nb_e, TB>>>(src, dst, e);

    // Layer 0: ClusterGCN
    k_agg0 <<<nb_16, TB>>>((const float4*)x, n);
    k_gemm0<<<nb_g, 512, 128*68*4 + 32768>>>((const float4*)x, Wout, bout, Wroot, n);

    // Layer 1: GAT(64->64)
    k_gemm1<<<nb_g, 512, 128*68*4 + 16384>>>(W1, as1, ad1, n);
    k_gat_agg<64, false><<<nb_8, TB>>>(nullptr, nullptr, n);

    // Layer 2: GAT(64->32)
    k_gemm2<<<nb_g, 256, 128*68*4 + 8192>>>(W2, b1, as2, ad2, n);
    k_gat_agg<32, true><<<nb_4, TB>>>((float*)d_out, b2, n);
}